// round 9
// baseline (speedup 1.0000x reference)
#include <cuda_runtime.h>
#include <cstdint>

// DispCorrM via banded tf32 mma.sync (HMMA) GEMM. R9: 8 warps/CTA, one
// m16-tile per warp (40-float C), A operands gmem->register (no smem round
// trip), B in smem, 3 CTAs/SM.
// out[b,d,h,w] = (1/32) * sum_c L[c,w] * R[c,w-d]   (0 if w<d)
// Per CTA (b, h, w-tile of 128): D[m,n] = sum_c A[m,c]*B[n,c]
//   A[m,c] = L[c, w0+m]   (128 x 32)
//   B[n,c] = R[c, w0-64+n] (192 x 32, zero for w<0)
//   out[d, w0+m] = D[m, m+64-d]/32
// Band: per m16-tile mt only n in [16mt, 16mt+80) is needed (10 n8-tiles).

#define BB    4
#define CCH   32
#define HH    256
#define WW    512
#define DDISP 64
#define HW    ((size_t)HH * WW)

#define PAD  36     // uint32 per B row: fragment LDS bank-distinct (4g+t)
#define OPAD 132    // floats per staging row: conflict-free band STS

__device__ __forceinline__ uint32_t f2tf32(float v) {
    uint32_t t;
    asm("cvt.rna.tf32.f32 %0, %1;" : "=r"(t) : "f"(v));
    return t;
}

__device__ __forceinline__ void mma8(float* c, const uint32_t* a, uint32_t b0, uint32_t b1) {
    asm volatile(
        "mma.sync.aligned.m16n8k8.row.col.f32.tf32.tf32.f32 "
        "{%0,%1,%2,%3}, {%4,%5,%6,%7}, {%8,%9}, {%0,%1,%2,%3};"
        : "+f"(c[0]), "+f"(c[1]), "+f"(c[2]), "+f"(c[3])
        : "r"(a[0]), "r"(a[1]), "r"(a[2]), "r"(a[3]), "r"(b0), "r"(b1));
}

__global__ __launch_bounds__(256, 3)
void disp_corr_mma_kernel(const float* __restrict__ x, float* __restrict__ out) {
    __shared__ union {
        uint32_t B[192 * PAD];       // 27 KB (tf32 bit patterns)
        float O[DDISP * OPAD];       // 33.8 KB staging (aliased after mainloop)
    } sm;

    const int tid  = threadIdx.x;
    const int lane = tid & 31;
    const int warp = tid >> 5;          // 0..7 (= m16-tile index)
    const int g    = lane >> 2;         // 0..7
    const int t    = lane & 3;          // 0..3
    const int tile = blockIdx.x;        // 0..3
    const int h    = blockIdx.y;
    const int b    = blockIdx.z;
    const int w0   = tile * 128;

    const float* Lg = x + (((size_t)b * 2 * CCH) * HH + h) * WW + w0;   // L[c][w0+m] at c*HW+m
    const float* Rg = x + (((size_t)b * 2 * CCH + CCH) * HH + h) * WW;  // R[c][w]    at c*HW+w

    // ---- B: load + transpose + tf32-convert into smem (rows n = tid < 192) ----
    if (tid < 192) {
        uint32_t* Br = &sm.B[tid * PAD];
        int wg = w0 - 64 + tid;
        if (wg >= 0) {
            #pragma unroll
            for (int c = 0; c < 32; c++)
                Br[c] = f2tf32(__ldg(Rg + (size_t)c * HW + wg));
        } else {
            #pragma unroll
            for (int c = 0; c < 32; c++) Br[c] = 0u;
        }
    }

    // ---- A: direct gmem -> register fragments (rows 16*warp+g, +8) ----
    // a[ks] = { A[g][t+8ks], A[g+8][t+8ks], A[g][t+8ks+4], A[g+8][t+8ks+4] }
    uint32_t afr[4][4];
    {
        const float* a0p = Lg + (16 * warp + g);        // + c*HW
        const float* a1p = a0p + 8;
        #pragma unroll
        for (int ks = 0; ks < 4; ks++) {
            afr[ks][0] = f2tf32(__ldg(a0p + (size_t)(t + 8 * ks) * HW));
            afr[ks][1] = f2tf32(__ldg(a1p + (size_t)(t + 8 * ks) * HW));
            afr[ks][2] = f2tf32(__ldg(a0p + (size_t)(t + 8 * ks + 4) * HW));
            afr[ks][3] = f2tf32(__ldg(a1p + (size_t)(t + 8 * ks + 4) * HW));
        }
    }
    __syncthreads();

    // ---- Mainloop: 10 n8-tiles, n_base = 16*warp + 8j ----
    const uint32_t* bp = &sm.B[(16 * warp + g) * PAD + t];

    float C[10][4];
    #pragma unroll
    for (int j = 0; j < 10; j++)
        #pragma unroll
        for (int r = 0; r < 4; r++) C[j][r] = 0.f;

    #pragma unroll
    for (int ks = 0; ks < 4; ks++) {
        #pragma unroll
        for (int j = 0; j < 10; j++) {
            uint32_t b0 = bp[j * 8 * PAD + 8 * ks];
            uint32_t b1 = bp[j * 8 * PAD + 8 * ks + 4];
            mma8(C[j], afr[ks], b0, b1);
        }
    }

    __syncthreads();   // all B fragment LDS done before aliasing smem as staging

    // ---- Band extraction: d = m + 64 - n = g - 8j - 2t + 64 (+row/col offsets) ----
    const float inv_c = 1.0f / 32.0f;
    {
        const int mbase = 16 * warp + g;
        #pragma unroll
        for (int j = 0; j < 10; j++) {
            const int dbase = g + 64 - 8 * j - 2 * t;
            if ((unsigned)dbase       < 64u) sm.O[dbase       * OPAD + mbase]     = C[j][0] * inv_c;
            if ((unsigned)(dbase - 1) < 64u) sm.O[(dbase - 1) * OPAD + mbase]     = C[j][1] * inv_c;
            if ((unsigned)(dbase + 8) < 64u) sm.O[(dbase + 8) * OPAD + mbase + 8] = C[j][2] * inv_c;
            if ((unsigned)(dbase + 7) < 64u) sm.O[(dbase + 7) * OPAD + mbase + 8] = C[j][3] * inv_c;
        }
    }
    __syncthreads();

    // ---- Coalesced store: 2048 float4s, 8 per thread; warp covers one d-row/pass ----
    float* op = out + (((size_t)b * DDISP) * HH + h) * WW + w0;
    #pragma unroll
    for (int i = 0; i < 8; i++) {
        const int d = 8 * i + warp;
        float4 v = *(const float4*)&sm.O[d * OPAD + 4 * lane];
        *(float4*)(op + (size_t)d * HW + 4 * lane) = v;
    }
}

extern "C" void kernel_launch(void* const* d_in, const int* in_sizes, int n_in,
                              void* d_out, int out_size) {
    const float* x = (const float*)d_in[0];
    float* out = (float*)d_out;
    dim3 grid(WW / 128, HH, BB);   // (4, 256, 4) = 4096 blocks
    disp_corr_mma_kernel<<<grid, 256>>>(x, out);
}

// round 10
// speedup vs baseline: 1.2941x; 1.2941x over previous
#include <cuda_runtime.h>
#include <cstdint>

// DispCorrM via banded tf32 mma.sync (HMMA) GEMM.
// R10: R8 geometry (128 thr, warp owns m16-tiles {2w,2w+1}, 4 CTAs/SM) with
// the load phase replaced by raw-layout cp.async (no transpose, no cvt, no
// STS chain); tf32 conversion happens at fragment build (LDS.32 + cvt.rna).
//
// out[b,d,h,w] = (1/32) * sum_c L[c,w] * R[c,w-d]   (0 if w<d)
// Per CTA (b, h, w-tile of 128): D[m,n] = sum_c A[c][m]*B[c][n]
//   A[c][m] = L[c, w0+m]      (smem rows of 128, stride 136: 8t+g banks)
//   B[c][n] = R[c, w0-64+n]   (smem rows of 192, stride 200: 8t+g banks)
//   out[d, w0+m] = D[m, m+64-d]/32
// Band: per m16-tile mt only n in [16mt, 16mt+80) needed (10 n8-tiles).

#define BB    4
#define CCH   32
#define HH    256
#define WW    512
#define DDISP 64
#define HW    ((size_t)HH * WW)

#define SA   136    // A row stride (floats); 136 mod 32 = 8 -> conflict-free frags
#define SB   200    // B row stride (floats); 200 mod 32 = 8
#define OPAD 132    // staging row stride (floats); conflict-free band STS (from R8)

__device__ __forceinline__ uint32_t f2tf32(float v) {
    uint32_t t;
    asm("cvt.rna.tf32.f32 %0, %1;" : "=r"(t) : "f"(v));
    return t;
}
__device__ __forceinline__ void cp16(uint32_t sa, const void* g, uint32_t src_bytes) {
    asm volatile("cp.async.cg.shared.global [%0], [%1], 16, %2;"
                 :: "r"(sa), "l"(g), "r"(src_bytes));
}
__device__ __forceinline__ void mma8(float* c, const uint32_t* a, uint32_t b0, uint32_t b1) {
    asm volatile(
        "mma.sync.aligned.m16n8k8.row.col.f32.tf32.tf32.f32 "
        "{%0,%1,%2,%3}, {%4,%5,%6,%7}, {%8,%9}, {%0,%1,%2,%3};"
        : "+f"(c[0]), "+f"(c[1]), "+f"(c[2]), "+f"(c[3])
        : "r"(a[0]), "r"(a[1]), "r"(a[2]), "r"(a[3]), "r"(b0), "r"(b1));
}

__global__ __launch_bounds__(128, 4)
void disp_corr_mma_kernel(const float* __restrict__ x, float* __restrict__ out) {
    __shared__ union {
        struct {
            float A[CCH * SA];       // 17.4 KB, raw fp32 L rows
            float B[CCH * SB];       // 25.6 KB, raw fp32 R rows (halo zero-filled)
        } in;
        float O[DDISP * OPAD];       // 33.8 KB staging (aliased after mainloop)
    } sm;

    const int tid  = threadIdx.x;
    const int lane = tid & 31;
    const int warp = tid >> 5;          // 0..3
    const int g    = lane >> 2;         // 0..7
    const int t    = lane & 3;          // 0..3
    const int tile = blockIdx.x;        // 0..3
    const int h    = blockIdx.y;
    const int b    = blockIdx.z;
    const int w0   = tile * 128;

    const float* Lg = x + (((size_t)b * 2 * CCH) * HH + h) * WW + w0;
    const float* Rg = x + (((size_t)b * 2 * CCH + CCH) * HH + h) * WW;

    // ---- cp.async raw tiles: A = 32 rows x 32 granules, B = 32 rows x 48 granules ----
    {
        const uint32_t abase = (uint32_t)__cvta_generic_to_shared(sm.in.A);
        #pragma unroll
        for (int k = 0; k < 8; k++) {                 // 1024 granules / 128 thr
            int idx = k * 128 + tid;
            int c = idx >> 5, q = idx & 31;
            cp16(abase + (c * SA + 4 * q) * 4, Lg + (size_t)c * HW + 4 * q, 16);
        }
        const uint32_t bbase = (uint32_t)__cvta_generic_to_shared(sm.in.B);
        #pragma unroll
        for (int k = 0; k < 12; k++) {                // 1536 granules / 128 thr
            int idx = k * 128 + tid;
            int c = idx / 48, q = idx % 48;
            int wg = w0 - 64 + 4 * q;                 // granule-aligned: all-in or all-out
            const float* src = Rg + (size_t)c * HW + (wg >= 0 ? wg : 0);
            cp16(bbase + (c * SB + 4 * q) * 4, src, wg >= 0 ? 16u : 0u);
        }
        asm volatile("cp.async.commit_group;");
        asm volatile("cp.async.wait_group 0;");
    }
    __syncthreads();

    // ---- Mainloop: warp owns m16-tiles {2w, 2w+1}; B tiles j=0..11 shared ----
    // Fragment element (row r, col k): A -> sm.in.A[k*SA + r], B -> sm.in.B[k*SB + n]
    const float* ap = &sm.in.A[t * SA + 32 * warp + g];   // + 8ks*SA (+4*SA), +8/+16/+24
    const float* bp = &sm.in.B[t * SB + 32 * warp + g];   // + 8ks*SB (+4*SB), +8j

    float C0[10][4], C1[10][4];
    #pragma unroll
    for (int j = 0; j < 10; j++)
        #pragma unroll
        for (int r = 0; r < 4; r++) { C0[j][r] = 0.f; C1[j][r] = 0.f; }

    #pragma unroll
    for (int ks = 0; ks < 4; ks++) {
        const float* a = ap + 8 * ks * SA;
        uint32_t a0[4], a1[4];
        a0[0] = f2tf32(a[0]);               a0[1] = f2tf32(a[8]);
        a0[2] = f2tf32(a[4 * SA]);          a0[3] = f2tf32(a[4 * SA + 8]);
        a1[0] = f2tf32(a[16]);              a1[1] = f2tf32(a[24]);
        a1[2] = f2tf32(a[4 * SA + 16]);     a1[3] = f2tf32(a[4 * SA + 24]);

        const float* bb = bp + 8 * ks * SB;
        #pragma unroll
        for (int j = 0; j < 12; j++) {
            uint32_t b0 = f2tf32(bb[8 * j]);
            uint32_t b1 = f2tf32(bb[4 * SB + 8 * j]);
            if (j < 10) mma8(C0[j], a0, b0, b1);
            if (j >= 2) mma8(C1[j - 2], a1, b0, b1);
        }
    }

    __syncthreads();   // operand LDS done before aliasing smem as staging

    // ---- Band extraction: d = m + 64 - n ----
    const float inv_c = 1.0f / 32.0f;
    #pragma unroll
    for (int half = 0; half < 2; half++) {
        const int mbase = 32 * warp + 16 * half + g;
        #pragma unroll
        for (int j = 0; j < 10; j++) {
            const float* Cr = half ? C1[j] : C0[j];
            const int dbase = g + 64 - 8 * j - 2 * t;
            if ((unsigned)dbase       < 64u) sm.O[dbase       * OPAD + mbase]     = Cr[0] * inv_c;
            if ((unsigned)(dbase - 1) < 64u) sm.O[(dbase - 1) * OPAD + mbase]     = Cr[1] * inv_c;
            if ((unsigned)(dbase + 8) < 64u) sm.O[(dbase + 8) * OPAD + mbase + 8] = Cr[2] * inv_c;
            if ((unsigned)(dbase + 7) < 64u) sm.O[(dbase + 7) * OPAD + mbase + 8] = Cr[3] * inv_c;
        }
    }
    __syncthreads();

    // ---- Coalesced store: warp handles d = warp + 4i, float4 per lane ----
    float* op = out + (((size_t)b * DDISP) * HH + h) * WW + w0;
    #pragma unroll
    for (int i = 0; i < 16; i++) {
        const int d = 4 * i + warp;
        float4 v = *(const float4*)&sm.O[d * OPAD + 4 * lane];
        *(float4*)(op + (size_t)d * HW + 4 * lane) = v;
    }
}

extern "C" void kernel_launch(void* const* d_in, const int* in_sizes, int n_in,
                              void* d_out, int out_size) {
    const float* x = (const float*)d_in[0];
    float* out = (float*)d_out;
    dim3 grid(WW / 128, HH, BB);   // (4, 256, 4) = 4096 blocks
    disp_corr_mma_kernel<<<grid, 128>>>(x, out);
}

// round 12
// speedup vs baseline: 1.3520x; 1.0447x over previous
#include <cuda_runtime.h>
#include <cstdint>

// DispCorrM via banded tf32 mma.sync (HMMA) GEMM.
// R11: R10 + K-split load/compute pipelining: channels 0-15 and 16-31 land in
// separate cp.async groups; ks{0,1} computes under the in-flight second group.
//
// out[b,d,h,w] = (1/32) * sum_c L[c,w] * R[c,w-d]   (0 if w<d)
// Per CTA (b, h, w-tile of 128): D[m,n] = sum_c A[c][m]*B[c][n]
//   A[c][m] = L[c, w0+m]      (smem rows of 128, stride 136: 8t+g banks)
//   B[c][n] = R[c, w0-64+n]   (smem rows of 192, stride 200: 8t+g banks)
//   out[d, w0+m] = D[m, m+64-d]/32
// Band: per m16-tile mt only n in [16mt, 16mt+80) needed (10 n8-tiles).

#define BB    4
#define CCH   32
#define HH    256
#define WW    512
#define DDISP 64
#define HW    ((size_t)HH * WW)

#define SA   136    // A row stride (floats); 136 mod 32 = 8 -> conflict-free frags
#define SB   200    // B row stride (floats); 200 mod 32 = 8
#define OPAD 132    // staging row stride (floats); conflict-free band STS

__device__ __forceinline__ uint32_t f2tf32(float v) {
    uint32_t t;
    asm("cvt.rna.tf32.f32 %0, %1;" : "=r"(t) : "f"(v));
    return t;
}
__device__ __forceinline__ void cp16(uint32_t sa, const void* g, uint32_t src_bytes) {
    asm volatile("cp.async.cg.shared.global [%0], [%1], 16, %2;"
                 :: "r"(sa), "l"(g), "r"(src_bytes));
}
__device__ __forceinline__ void mma8(float* c, const uint32_t* a, uint32_t b0, uint32_t b1) {
    asm volatile(
        "mma.sync.aligned.m16n8k8.row.col.f32.tf32.tf32.f32 "
        "{%0,%1,%2,%3}, {%4,%5,%6,%7}, {%8,%9}, {%0,%1,%2,%3};"
        : "+f"(c[0]), "+f"(c[1]), "+f"(c[2]), "+f"(c[3])
        : "r"(a[0]), "r"(a[1]), "r"(a[2]), "r"(a[3]), "r"(b0), "r"(b1));
}

__global__ __launch_bounds__(128, 4)
void disp_corr_mma_kernel(const float* __restrict__ x, float* __restrict__ out) {
    __shared__ union {
        struct {
            float A[CCH * SA];       // 17.4 KB, raw fp32 L rows
            float B[CCH * SB];       // 25.6 KB, raw fp32 R rows (halo zero-filled)
        } in;
        float O[DDISP * OPAD];       // 33.8 KB staging (aliased after mainloop)
    } sm;

    const int tid  = threadIdx.x;
    const int lane = tid & 31;
    const int warp = tid >> 5;          // 0..3
    const int g    = lane >> 2;         // 0..7
    const int t    = lane & 3;          // 0..3
    const int tile = blockIdx.x;        // 0..3
    const int h    = blockIdx.y;
    const int b    = blockIdx.z;
    const int w0   = tile * 128;

    const float* Lg = x + (((size_t)b * 2 * CCH) * HH + h) * WW + w0;
    const float* Rg = x + (((size_t)b * 2 * CCH + CCH) * HH + h) * WW;

    const uint32_t abase = (uint32_t)__cvta_generic_to_shared(sm.in.A);
    const uint32_t bbase = (uint32_t)__cvta_generic_to_shared(sm.in.B);

    // ---- K-chunk loader: channels [c0, c0+16). A: 512 granules, B: 768. ----
    auto load_half = [&](int c0) {
        #pragma unroll
        for (int k = 0; k < 4; k++) {                 // A: 512 granules / 128 thr
            int idx = k * 128 + tid;
            int c = c0 + (idx >> 5), q = idx & 31;
            cp16(abase + (c * SA + 4 * q) * 4, Lg + (size_t)c * HW + 4 * q, 16);
        }
        #pragma unroll
        for (int k = 0; k < 6; k++) {                 // B: 768 granules / 128 thr
            int idx = k * 128 + tid;
            int c = c0 + idx / 48, q = idx % 48;
            int wg = w0 - 64 + 4 * q;                 // granule-aligned: all-in or all-out
            const float* src = Rg + (size_t)c * HW + (wg >= 0 ? wg : 0);
            cp16(bbase + (c * SB + 4 * q) * 4, src, wg >= 0 ? 16u : 0u);
        }
        asm volatile("cp.async.commit_group;");
    };

    load_half(0);    // group 0: channels 0-15  (covers ks 0,1)
    load_half(16);   // group 1: channels 16-31 (covers ks 2,3)

    // ---- Mainloop: warp owns m16-tiles {2w, 2w+1}; B tiles j=0..11 shared ----
    const float* ap = &sm.in.A[t * SA + 32 * warp + g];
    const float* bp = &sm.in.B[t * SB + 32 * warp + g];

    float C0[10][4], C1[10][4];
    #pragma unroll
    for (int j = 0; j < 10; j++)
        #pragma unroll
        for (int r = 0; r < 4; r++) { C0[j][r] = 0.f; C1[j][r] = 0.f; }

    asm volatile("cp.async.wait_group 1;");   // chunk 0 landed
    __syncthreads();

    #pragma unroll
    for (int ks = 0; ks < 4; ks++) {
        if (ks == 2) {
            asm volatile("cp.async.wait_group 0;");   // chunk 1 landed
            __syncthreads();
        }
        const float* a = ap + 8 * ks * SA;
        uint32_t a0[4], a1[4];
        a0[0] = f2tf32(a[0]);               a0[1] = f2tf32(a[8]);
        a0[2] = f2tf32(a[4 * SA]);          a0[3] = f2tf32(a[4 * SA + 8]);
        a1[0] = f2tf32(a[16]);              a1[1] = f2tf32(a[24]);
        a1[2] = f2tf32(a[4 * SA + 16]);     a1[3] = f2tf32(a[4 * SA + 24]);

        const float* bb = bp + 8 * ks * SB;
        #pragma unroll
        for (int j = 0; j < 12; j++) {
            uint32_t b0 = f2tf32(bb[8 * j]);
            uint32_t b1 = f2tf32(bb[4 * SB + 8 * j]);
            if (j < 10) mma8(C0[j], a0, b0, b1);
            if (j >= 2) mma8(C1[j - 2], a1, b0, b1);
        }
    }

    __syncthreads();   // operand LDS done before aliasing smem as staging

    // ---- Band extraction: d = m + 64 - n ----
    const float inv_c = 1.0f / 32.0f;
    #pragma unroll
    for (int half = 0; half < 2; half++) {
        const int mbase = 32 * warp + 16 * half + g;
        #pragma unroll
        for (int j = 0; j < 10; j++) {
            const float* Cr = half ? C1[j] : C0[j];
            const int dbase = g + 64 - 8 * j - 2 * t;
            if ((unsigned)dbase       < 64u) sm.O[dbase       * OPAD + mbase]     = Cr[0] * inv_c;
            if ((unsigned)(dbase - 1) < 64u) sm.O[(dbase - 1) * OPAD + mbase]     = Cr[1] * inv_c;
            if ((unsigned)(dbase + 8) < 64u) sm.O[(dbase + 8) * OPAD + mbase + 8] = Cr[2] * inv_c;
            if ((unsigned)(dbase + 7) < 64u) sm.O[(dbase + 7) * OPAD + mbase + 8] = Cr[3] * inv_c;
        }
    }
    __syncthreads();

    // ---- Coalesced store: warp handles d = warp + 4i, float4 per lane ----
    float* op = out + (((size_t)b * DDISP) * HH + h) * WW + w0;
    #pragma unroll
    for (int i = 0; i < 16; i++) {
        const int d = 4 * i + warp;
        float4 v = *(const float4*)&sm.O[d * OPAD + 4 * lane];
        *(float4*)(op + (size_t)d * HW + 4 * lane) = v;
    }
}

extern "C" void kernel_launch(void* const* d_in, const int* in_sizes, int n_in,
                              void* d_out, int out_size) {
    const float* x = (const float*)d_in[0];
    float* out = (float*)d_out;
    dim3 grid(WW / 128, HH, BB);   // (4, 256, 4) = 4096 blocks
    disp_corr_mma_kernel<<<grid, 128>>>(x, out);
}